// round 15
// baseline (speedup 1.0000x reference)
#include <cuda_runtime.h>
#include <cuda_fp16.h>
#include <cstdint>

#define BATCH 2
#define SEQ 2048
#define HEADS 16
#define DH 64
#define DMODEL 1024
#define MROWS (BATCH*SEQ)   // 4096
#define KDIM 1024
#define NQKV 3072
#define NBH (BATCH*HEADS)   // 32

// ---------------- device scratch (allocation-free rule) ----------------
__device__ __half g_Qh[NBH*SEQ*DH];
__device__ __half g_Kh[NBH*SEQ*DH];
__device__ __half g_Vh[NBH*SEQ*DH];           // V fp16 [bh][s][d]
__device__ __half g_x_h [MROWS*KDIM];
__device__ __half g_wq_h[NQKV*KDIM];          // Wqkv^T [N,K] fp16
__device__ __half g_wo_h[DMODEL*KDIM];        // Wout^T [N,K] fp16
__device__ __half g_attn_h[MROWS*DMODEL];

// ---------------- helpers ----------------
__device__ __forceinline__ uint32_t smem_u32(const void* p) {
    uint32_t a;
    asm("{ .reg .u64 t; cvta.to.shared.u64 t, %1; cvt.u32.u64 %0, t; }" : "=r"(a) : "l"(p));
    return a;
}
__device__ __forceinline__ void cpa16(uint32_t dst, const void* src) {
    asm volatile("cp.async.cg.shared.global [%0], [%1], 16;" :: "r"(dst), "l"(src) : "memory");
}
__device__ __forceinline__ void cpa_commit() {
    asm volatile("cp.async.commit_group;" ::: "memory");
}
__device__ __forceinline__ void ldsm_x4(uint32_t* r, uint32_t addr) {
    asm volatile("ldmatrix.sync.aligned.m8n8.x4.shared.b16 {%0,%1,%2,%3}, [%4];"
        : "=r"(r[0]), "=r"(r[1]), "=r"(r[2]), "=r"(r[3]) : "r"(addr));
}
__device__ __forceinline__ void ldsm_x4_t(uint32_t* r, uint32_t addr) {
    asm volatile("ldmatrix.sync.aligned.m8n8.x4.trans.shared.b16 {%0,%1,%2,%3}, [%4];"
        : "=r"(r[0]), "=r"(r[1]), "=r"(r[2]), "=r"(r[3]) : "r"(addr));
}
__device__ __forceinline__ void mma_f16(float* c, const uint32_t* a, const uint32_t* b) {
    asm volatile(
        "mma.sync.aligned.m16n8k16.row.col.f32.f16.f16.f32 "
        "{%0,%1,%2,%3}, {%4,%5,%6,%7}, {%8,%9}, {%0,%1,%2,%3};"
        : "+f"(c[0]), "+f"(c[1]), "+f"(c[2]), "+f"(c[3])
        : "r"(a[0]), "r"(a[1]), "r"(a[2]), "r"(a[3]), "r"(b[0]), "r"(b[1]));
}
__device__ __forceinline__ uint32_t pack_h2(__half a, __half b) {
    return (uint32_t)__half_as_ushort(a) | ((uint32_t)__half_as_ushort(b) << 16);
}

// ---------------- fused preprocessing (round-14 proven) ----------------
__device__ __forceinline__ void do_transpose(const float* __restrict__ W,
                                             __half* __restrict__ th,
                                             int K, int N, int bx, int by, int tid) {
    __shared__ float t[32][33];
    const int tx = tid & 31, ty = tid >> 5;
    #pragma unroll
    for (int r = 0; r < 4; r++) {
        int k = by * 32 + ty + r * 8;
        int n = bx * 32 + tx;
        t[ty + r * 8][tx] = W[(size_t)k * N + n];
    }
    __syncthreads();
    #pragma unroll
    for (int r = 0; r < 4; r++) {
        int n = bx * 32 + ty + r * 8;
        int k = by * 32 + tx;
        th[(size_t)n * K + k] = __float2half(t[tx][ty + r * 8]);
    }
}

__global__ __launch_bounds__(256)
void prep_kernel(const float* __restrict__ x, const float* __restrict__ Wqkv,
                 const float* __restrict__ Wout,
                 __half* __restrict__ xh, __half* __restrict__ wqh,
                 __half* __restrict__ woh)
{
    const int blk = blockIdx.x;
    const int tid = threadIdx.x;
    if (blk < 4096) {
        const size_t i = (size_t)blk * 256 + tid;
        float4 v = ((const float4*)x)[i];
        ((uint2*)xh)[i] = make_uint2(pack_h2(__float2half(v.x), __float2half(v.y)),
                                     pack_h2(__float2half(v.z), __float2half(v.w)));
    } else if (blk < 7168) {
        const int b2 = blk - 4096;
        do_transpose(Wqkv, wqh, KDIM, NQKV, b2 % 96, b2 / 96, tid);
    } else {
        const int b2 = blk - 7168;
        do_transpose(Wout, woh, KDIM, DMODEL, b2 & 31, b2 >> 5, tid);
    }
}

// ---------------- pure fp16 GEMM (round-12 proven) ----------------
#define BK 32
#define ROWB 80
#define MATB (128*ROWB)
#define OFF_A  0
#define OFF_B  MATB
#define STAGEB (2*MATB)
#define NCH (KDIM/BK)
#define SMEM_GEMM (2*STAGEB)

template<int EPI>
__global__ __launch_bounds__(128, 2)
void mma_gemm(const __half* __restrict__ A, const __half* __restrict__ B,
              const float* __restrict__ bias, float* __restrict__ Cout)
{
    extern __shared__ char smem[];
    const uint32_t sb = smem_u32(smem);
    const int tid = threadIdx.x;
    const int lane = tid & 31;
    const int wid = tid >> 5;
    const int rowBase = blockIdx.y * 128;
    const int colBase = blockIdx.x * 128;
    const int mBase = (wid & 1) * 64;
    const int nBase = (wid >> 1) * 64;

    auto issue = [&](int c, int st) {
        const int k0 = c * BK;
        const uint32_t base = sb + st * STAGEB;
        #pragma unroll
        for (int j = 0; j < 4; j++) {
            const int u = tid + j * 128;
            const int r = u >> 2, q = u & 3;
            const uint32_t so = (uint32_t)(r * ROWB + q * 16);
            const size_t offA = (size_t)(rowBase + r) * KDIM + k0 + q * 8;
            const size_t offB = (size_t)(colBase + r) * KDIM + k0 + q * 8;
            cpa16(base + OFF_A + so, A + offA);
            cpa16(base + OFF_B + so, B + offB);
        }
        cpa_commit();
    };

    float acc[4][8][4];
    #pragma unroll
    for (int i = 0; i < 4; i++)
        #pragma unroll
        for (int j = 0; j < 8; j++)
            #pragma unroll
            for (int r = 0; r < 4; r++) acc[i][j][r] = 0.f;

    issue(0, 0);
    issue(1, 1);

    const int ja = lane >> 3;
    const int ra = lane & 7;
    const uint32_t aRowCol = (uint32_t)(((ja & 1) * 8 + ra) * ROWB + (ja >> 1) * 16);
    const uint32_t bRowCol = (uint32_t)((((lane >> 4) * 8) + ra) * ROWB + ((lane >> 3) & 1) * 16);

    for (int c = 0; c < NCH; c++) {
        if (c == NCH - 1)
            asm volatile("cp.async.wait_group 0;" ::: "memory");
        else
            asm volatile("cp.async.wait_group 1;" ::: "memory");
        __syncthreads();

        const int st = c & 1;
        const uint32_t base = sb + st * STAGEB;

        #pragma unroll
        for (int kb = 0; kb < 2; kb++) {
            uint32_t ah[4][4];
            #pragma unroll
            for (int mf = 0; mf < 4; mf++) {
                const uint32_t off = (uint32_t)((mBase + mf * 16) * ROWB + kb * 32) + aRowCol;
                ldsm_x4(ah[mf], base + OFF_A + off);
            }
            uint32_t bfr[8][2];
            #pragma unroll
            for (int nf2 = 0; nf2 < 4; nf2++) {
                const uint32_t off = (uint32_t)((nBase + nf2 * 16) * ROWB + kb * 32) + bRowCol;
                uint32_t t4[4];
                ldsm_x4(t4, base + OFF_B + off);
                bfr[nf2*2][0] = t4[0]; bfr[nf2*2][1] = t4[1];
                bfr[nf2*2+1][0] = t4[2]; bfr[nf2*2+1][1] = t4[3];
            }
            #pragma unroll
            for (int mf = 0; mf < 4; mf++)
                #pragma unroll
                for (int nf = 0; nf < 8; nf++)
                    mma_f16(acc[mf][nf], ah[mf], bfr[nf]);
        }
        __syncthreads();
        if (c + 2 < NCH) issue(c + 2, st);
    }

    #pragma unroll
    for (int mf = 0; mf < 4; mf++) {
        #pragma unroll
        for (int rp = 0; rp < 2; rp++) {
            const int m = rowBase + mBase + mf * 16 + (lane >> 2) + rp * 8;
            const int b = m >> 11;
            const int s_ = m & (SEQ - 1);
            #pragma unroll
            for (int nf = 0; nf < 8; nf++) {
                const int n0 = colBase + nBase + nf * 8 + (lane & 3) * 2;
                const float v0 = acc[mf][nf][rp * 2 + 0] + bias[n0];
                const float v1 = acc[mf][nf][rp * 2 + 1] + bias[n0 + 1];
                if (EPI == 0) {
                    const int h = n0 / 192;
                    const int rr = n0 - h * 192;
                    const size_t bhBase = (size_t)(b * HEADS + h) * SEQ + s_;
                    const uint32_t pk = pack_h2(__float2half(v0), __float2half(v1));
                    if (rr < 64) {
                        *(uint32_t*)&g_Qh[bhBase * DH + rr] = pk;
                    } else if (rr < 128) {
                        *(uint32_t*)&g_Kh[bhBase * DH + (rr - 64)] = pk;
                    } else {
                        *(uint32_t*)&g_Vh[bhBase * DH + (rr - 128)] = pk;
                    }
                } else {
                    *(float2*)&Cout[(size_t)m * DMODEL + n0] = make_float2(v0, v1);
                }
            }
        }
    }
}

// ---------------- pure fp16 flash attention, kv-tile 128 ----------------
#define ROW2 144
#define FQ_BYTES (128*ROW2)            // 18432 (Q)
#define FK2_BYTES (128*ROW2)           // 18432 per K/V tile (128 rows)
#define FO_Q 0
#define FO_STAGE FQ_BYTES
#define FSTAGEB (2*FK2_BYTES)          // 36864 (K | V)
#define SMEM_FLASH (FO_STAGE + 2*FSTAGEB)   // 92160
#define NQT (SEQ/128)          // 16

__global__ __launch_bounds__(256, 2)
void flash_mma()
{
    extern __shared__ char smem[];
    const uint32_t sb = smem_u32(smem);
    const int tid = threadIdx.x;
    const int lane = tid & 31;
    const int w = tid >> 5;
    const int bx = blockIdx.x;       // 0..7
    const int bh = blockIdx.y;

    const int lr = lane >> 2;
    const int lc = (lane & 3) * 2;

    const __half* Qh = g_Qh + (size_t)bh * SEQ * DH;
    const __half* Kh = g_Kh + (size_t)bh * SEQ * DH;
    const __half* Vh = g_Vh + (size_t)bh * SEQ * DH;

    const int ja = lane >> 3;
    const int ra = lane & 7;
    const uint32_t aRowCol = (uint32_t)(((ja & 1) * 8 + ra) * ROW2 + (ja >> 1) * 16);
    const uint32_t bRowCol = (uint32_t)((((lane >> 4) * 8) + ra) * ROW2 + ((lane >> 3) & 1) * 16);
    const uint32_t qWarpOff = (uint32_t)(w * 16) * ROW2 + aRowCol;
    const uint32_t vTransOff = (uint32_t)((lane & 15) * ROW2 + (lane >> 4) * 16);

    auto issueKV = [&](int t, int st) {
        const int kv0 = t * 128;
        const uint32_t base = sb + FO_STAGE + st * FSTAGEB;
        #pragma unroll
        for (int j = 0; j < 4; j++) {
            const int u = tid + j * 256;
            const int r = u >> 3, c = u & 7;
            const uint32_t so = (uint32_t)(r * ROW2 + c * 16);
            const size_t off = (size_t)(kv0 + r) * DH + c * 8;
            cpa16(base + 0 * FK2_BYTES + so, Kh + off);
            cpa16(base + 1 * FK2_BYTES + so, Vh + off);
        }
        cpa_commit();
    };

    #pragma unroll 1
    for (int rep = 0; rep < 2; rep++) {
        const int qt = (rep == 0) ? bx : (NQT - 1 - bx);
        const int qb = qt * 128;
        const int nt = qt + 1;             // kv-128 steps

        #pragma unroll
        for (int j = 0; j < 4; j++) {
            const int u = tid + j * 256;
            const int r = u >> 3, c = u & 7;
            const uint32_t so = (uint32_t)(r * ROW2 + c * 16);
            cpa16(sb + FO_Q + so, Qh + (size_t)(qb + r) * DH + c * 8);
        }
        issueKV(0, 0);
        if (nt > 1) issueKV(1, 1);
        else cpa_commit();   // keep group-count parity for wait_group 1

        float oacc[8][4];
        #pragma unroll
        for (int nf = 0; nf < 8; nf++)
            #pragma unroll
            for (int r = 0; r < 4; r++) oacc[nf][r] = 0.f;
        float m0 = -1e30f, m1 = -1e30f, l0 = 0.f, l1 = 0.f;

        for (int t = 0; t < nt; t++) {
            if (t == nt - 1)
                asm volatile("cp.async.wait_group 0;" ::: "memory");
            else
                asm volatile("cp.async.wait_group 1;" ::: "memory");
            __syncthreads();

            const int kv0 = t * 128;
            const int st = t & 1;
            const uint32_t base = sb + FO_STAGE + st * FSTAGEB;

            {
                float sacc[16][4];
                #pragma unroll
                for (int nf = 0; nf < 16; nf++)
                    #pragma unroll
                    for (int r = 0; r < 4; r++) sacc[nf][r] = 0.f;

                // ---- S = Q K^T over 128 kv cols ----
                #pragma unroll
                for (int kf = 0; kf < 4; kf++) {
                    uint32_t qh4[4];
                    ldsm_x4(qh4, sb + FO_Q + qWarpOff + kf * 32);
                    uint32_t bb[16][2];
                    #pragma unroll
                    for (int nf2 = 0; nf2 < 8; nf2++) {
                        uint32_t t4[4];
                        ldsm_x4(t4, base + 0 * FK2_BYTES +
                                (uint32_t)(nf2 * 16) * ROW2 + kf * 32 + bRowCol);
                        bb[nf2*2][0] = t4[0]; bb[nf2*2][1] = t4[1];
                        bb[nf2*2+1][0] = t4[2]; bb[nf2*2+1][1] = t4[3];
                    }
                    #pragma unroll
                    for (int nf = 0; nf < 16; nf++)
                        mma_f16(sacc[nf], qh4, bb[nf]);
                }

                const bool needMask = (kv0 + 127) > (qb + w * 16);
                const int row0 = qb + w * 16 + lr;
                const int row1 = row0 + 8;
                #pragma unroll
                for (int nf = 0; nf < 16; nf++) {
                    const int c0 = kv0 + nf * 8 + lc;
                    #pragma unroll
                    for (int r = 0; r < 4; r++) {
                        float v = sacc[nf][r] * 0.125f;
                        if (needMask) {
                            const int col = c0 + (r & 1);
                            const int row = (r < 2) ? row0 : row1;
                            if (col > row) v = -1e30f;
                        }
                        sacc[nf][r] = v;
                    }
                }

                float mx0 = -1e30f, mx1 = -1e30f;
                #pragma unroll
                for (int nf = 0; nf < 16; nf++) {
                    mx0 = fmaxf(mx0, fmaxf(sacc[nf][0], sacc[nf][1]));
                    mx1 = fmaxf(mx1, fmaxf(sacc[nf][2], sacc[nf][3]));
                }
                mx0 = fmaxf(mx0, __shfl_xor_sync(0xffffffffu, mx0, 1));
                mx0 = fmaxf(mx0, __shfl_xor_sync(0xffffffffu, mx0, 2));
                mx1 = fmaxf(mx1, __shfl_xor_sync(0xffffffffu, mx1, 1));
                mx1 = fmaxf(mx1, __shfl_xor_sync(0xffffffffu, mx1, 2));
                const float nm0 = fmaxf(m0, mx0);
                const float nm1 = fmaxf(m1, mx1);
                const float corr0 = __expf(m0 - nm0);
                const float corr1 = __expf(m1 - nm1);
                m0 = nm0; m1 = nm1;

                float rs0 = 0.f, rs1 = 0.f;
                #pragma unroll
                for (int nf = 0; nf < 16; nf++) {
                    float p0 = __expf(sacc[nf][0] - m0);
                    float p1 = __expf(sacc[nf][1] - m0);
                    float p2 = __expf(sacc[nf][2] - m1);
                    float p3 = __expf(sacc[nf][3] - m1);
                    sacc[nf][0] = p0; sacc[nf][1] = p1;
                    sacc[nf][2] = p2; sacc[nf][3] = p3;
                    rs0 += p0 + p1; rs1 += p2 + p3;
                }
                rs0 += __shfl_xor_sync(0xffffffffu, rs0, 1);
                rs0 += __shfl_xor_sync(0xffffffffu, rs0, 2);
                rs1 += __shfl_xor_sync(0xffffffffu, rs1, 1);
                rs1 += __shfl_xor_sync(0xffffffffu, rs1, 2);
                l0 = l0 * corr0 + rs0;
                l1 = l1 * corr1 + rs1;

                #pragma unroll
                for (int nf = 0; nf < 8; nf++) {
                    oacc[nf][0] *= corr0; oacc[nf][1] *= corr0;
                    oacc[nf][2] *= corr1; oacc[nf][3] *= corr1;
                }

                // ---- O += P * V (kv length 128 -> 8 kf), V via ldsm.trans ----
                #pragma unroll
                for (int kf = 0; kf < 8; kf++) {
                    uint32_t ph[4];
                    ph[0] = pack_h2(__float2half(sacc[2*kf][0]),   __float2half(sacc[2*kf][1]));
                    ph[1] = pack_h2(__float2half(sacc[2*kf][2]),   __float2half(sacc[2*kf][3]));
                    ph[2] = pack_h2(__float2half(sacc[2*kf+1][0]), __float2half(sacc[2*kf+1][1]));
                    ph[3] = pack_h2(__float2half(sacc[2*kf+1][2]), __float2half(sacc[2*kf+1][3]));

                    uint32_t bv[8][2];
                    #pragma unroll
                    for (int nf2 = 0; nf2 < 4; nf2++) {
                        uint32_t t4[4];
                        ldsm_x4_t(t4, base + 1 * FK2_BYTES +
                                  (uint32_t)(kf * 16) * ROW2 + nf2 * 32 + vTransOff);
                        bv[nf2*2][0] = t4[0]; bv[nf2*2][1] = t4[1];
                        bv[nf2*2+1][0] = t4[2]; bv[nf2*2+1][1] = t4[3];
                    }
                    #pragma unroll
                    for (int nf = 0; nf < 8; nf++)
                        mma_f16(oacc[nf], ph, bv[nf]);
                }
            }

            __syncthreads();
            if (t + 2 < nt) issueKV(t + 2, st);
        }

        const float inv0 = 1.f / l0;
        const float inv1 = 1.f / l1;
        const int b = bh >> 4;
        const int h = bh & 15;
        const int row0 = qb + w * 16 + lr;
        const int row1 = row0 + 8;
        #pragma unroll
        for (int nf = 0; nf < 8; nf++) {
            const int col = h * 64 + nf * 8 + lc;
            const float v0 = oacc[nf][0] * inv0, v1 = oacc[nf][1] * inv0;
            const float v2 = oacc[nf][2] * inv1, v3 = oacc[nf][3] * inv1;
            const size_t i0 = ((size_t)(b * SEQ + row0)) * DMODEL + col;
            const size_t i1 = ((size_t)(b * SEQ + row1)) * DMODEL + col;
            *(uint32_t*)&g_attn_h[i0] = pack_h2(__float2half(v0), __float2half(v1));
            *(uint32_t*)&g_attn_h[i1] = pack_h2(__float2half(v2), __float2half(v3));
        }
        __syncthreads();
    }
}

// ---------------------------------------------------------------------------
extern "C" void kernel_launch(void* const* d_in, const int* in_sizes, int n_in,
                              void* d_out, int out_size)
{
    (void)in_sizes; (void)n_in; (void)out_size;
    const float* x    = (const float*)d_in[0];
    const float* Wqkv = (const float*)d_in[1];
    const float* bqkv = (const float*)d_in[2];
    const float* Wout = (const float*)d_in[3];
    const float* bout = (const float*)d_in[4];
    float* out = (float*)d_out;

    __half *xh, *wqh, *woh, *ah;
    cudaGetSymbolAddress((void**)&xh,  g_x_h);
    cudaGetSymbolAddress((void**)&wqh, g_wq_h);
    cudaGetSymbolAddress((void**)&woh, g_wo_h);
    cudaGetSymbolAddress((void**)&ah,  g_attn_h);

    cudaFuncSetAttribute(mma_gemm<0>, cudaFuncAttributeMaxDynamicSharedMemorySize, SMEM_GEMM);
    cudaFuncSetAttribute(mma_gemm<1>, cudaFuncAttributeMaxDynamicSharedMemorySize, SMEM_GEMM);
    cudaFuncSetAttribute(flash_mma, cudaFuncAttributeMaxDynamicSharedMemorySize, SMEM_FLASH);

    prep_kernel<<<8192, 256>>>(x, Wqkv, Wout, xh, wqh, woh);

    // QKV projection (pure fp16) -> Q/K/V fp16
    mma_gemm<0><<<dim3(NQKV / 128, MROWS / 128), 128, SMEM_GEMM>>>(
        xh, wqh, bqkv, nullptr);

    // pure fp16 causal flash attention, kv-tile 128, pairing-balanced
    flash_mma<<<dim3(NQT / 2, NBH), 256, SMEM_FLASH>>>();

    // output projection -> d_out
    mma_gemm<1><<<dim3(DMODEL / 128, MROWS / 128), 128, SMEM_GEMM>>>(
        ah, woh, bout, out);
}

// round 16
// speedup vs baseline: 1.0490x; 1.0490x over previous
#include <cuda_runtime.h>
#include <cuda_fp16.h>
#include <cstdint>

#define BATCH 2
#define SEQ 2048
#define HEADS 16
#define DH 64
#define DMODEL 1024
#define MROWS (BATCH*SEQ)   // 4096
#define KDIM 1024
#define NQKV 3072
#define NBH (BATCH*HEADS)   // 32

// ---------------- device scratch (allocation-free rule) ----------------
__device__ __half g_Qh[NBH*SEQ*DH];
__device__ __half g_Kh[NBH*SEQ*DH];
__device__ __half g_Vh[NBH*SEQ*DH];           // V fp16 [bh][s][d]
__device__ __half g_x_h [MROWS*KDIM];
__device__ __half g_wq_h[NQKV*KDIM];          // Wqkv^T [N,K] fp16
__device__ __half g_wo_h[DMODEL*KDIM];        // Wout^T [N,K] fp16
__device__ __half g_attn_h[MROWS*DMODEL];

// ---------------- helpers ----------------
__device__ __forceinline__ uint32_t smem_u32(const void* p) {
    uint32_t a;
    asm("{ .reg .u64 t; cvta.to.shared.u64 t, %1; cvt.u32.u64 %0, t; }" : "=r"(a) : "l"(p));
    return a;
}
__device__ __forceinline__ void cpa16(uint32_t dst, const void* src) {
    asm volatile("cp.async.cg.shared.global [%0], [%1], 16;" :: "r"(dst), "l"(src) : "memory");
}
__device__ __forceinline__ void cpa_commit() {
    asm volatile("cp.async.commit_group;" ::: "memory");
}
__device__ __forceinline__ void ldsm_x4(uint32_t* r, uint32_t addr) {
    asm volatile("ldmatrix.sync.aligned.m8n8.x4.shared.b16 {%0,%1,%2,%3}, [%4];"
        : "=r"(r[0]), "=r"(r[1]), "=r"(r[2]), "=r"(r[3]) : "r"(addr));
}
__device__ __forceinline__ void ldsm_x4_t(uint32_t* r, uint32_t addr) {
    asm volatile("ldmatrix.sync.aligned.m8n8.x4.trans.shared.b16 {%0,%1,%2,%3}, [%4];"
        : "=r"(r[0]), "=r"(r[1]), "=r"(r[2]), "=r"(r[3]) : "r"(addr));
}
__device__ __forceinline__ void mma_f16(float* c, const uint32_t* a, const uint32_t* b) {
    asm volatile(
        "mma.sync.aligned.m16n8k16.row.col.f32.f16.f16.f32 "
        "{%0,%1,%2,%3}, {%4,%5,%6,%7}, {%8,%9}, {%0,%1,%2,%3};"
        : "+f"(c[0]), "+f"(c[1]), "+f"(c[2]), "+f"(c[3])
        : "r"(a[0]), "r"(a[1]), "r"(a[2]), "r"(a[3]), "r"(b[0]), "r"(b[1]));
}
__device__ __forceinline__ uint32_t pack_h2(__half a, __half b) {
    return (uint32_t)__half_as_ushort(a) | ((uint32_t)__half_as_ushort(b) << 16);
}

// ---------------- fused preprocessing (round-14 proven) ----------------
__device__ __forceinline__ void do_transpose(const float* __restrict__ W,
                                             __half* __restrict__ th,
                                             int K, int N, int bx, int by, int tid) {
    __shared__ float t[32][33];
    const int tx = tid & 31, ty = tid >> 5;
    #pragma unroll
    for (int r = 0; r < 4; r++) {
        int k = by * 32 + ty + r * 8;
        int n = bx * 32 + tx;
        t[ty + r * 8][tx] = W[(size_t)k * N + n];
    }
    __syncthreads();
    #pragma unroll
    for (int r = 0; r < 4; r++) {
        int n = bx * 32 + ty + r * 8;
        int k = by * 32 + tx;
        th[(size_t)n * K + k] = __float2half(t[tx][ty + r * 8]);
    }
}

__global__ __launch_bounds__(256)
void prep_kernel(const float* __restrict__ x, const float* __restrict__ Wqkv,
                 const float* __restrict__ Wout,
                 __half* __restrict__ xh, __half* __restrict__ wqh,
                 __half* __restrict__ woh)
{
    const int blk = blockIdx.x;
    const int tid = threadIdx.x;
    if (blk < 4096) {
        const size_t i = (size_t)blk * 256 + tid;
        float4 v = ((const float4*)x)[i];
        ((uint2*)xh)[i] = make_uint2(pack_h2(__float2half(v.x), __float2half(v.y)),
                                     pack_h2(__float2half(v.z), __float2half(v.w)));
    } else if (blk < 7168) {
        const int b2 = blk - 4096;
        do_transpose(Wqkv, wqh, KDIM, NQKV, b2 % 96, b2 / 96, tid);
    } else {
        const int b2 = blk - 7168;
        do_transpose(Wout, woh, KDIM, DMODEL, b2 & 31, b2 >> 5, tid);
    }
}

// ---------------- pure fp16 GEMM (round-12 proven) ----------------
#define BK 32
#define ROWB 80
#define MATB (128*ROWB)
#define OFF_A  0
#define OFF_B  MATB
#define STAGEB (2*MATB)
#define NCH (KDIM/BK)
#define SMEM_GEMM (2*STAGEB)

template<int EPI>
__global__ __launch_bounds__(128, 2)
void mma_gemm(const __half* __restrict__ A, const __half* __restrict__ B,
              const float* __restrict__ bias, float* __restrict__ Cout)
{
    extern __shared__ char smem[];
    const uint32_t sb = smem_u32(smem);
    const int tid = threadIdx.x;
    const int lane = tid & 31;
    const int wid = tid >> 5;
    const int rowBase = blockIdx.y * 128;
    const int colBase = blockIdx.x * 128;
    const int mBase = (wid & 1) * 64;
    const int nBase = (wid >> 1) * 64;

    auto issue = [&](int c, int st) {
        const int k0 = c * BK;
        const uint32_t base = sb + st * STAGEB;
        #pragma unroll
        for (int j = 0; j < 4; j++) {
            const int u = tid + j * 128;
            const int r = u >> 2, q = u & 3;
            const uint32_t so = (uint32_t)(r * ROWB + q * 16);
            const size_t offA = (size_t)(rowBase + r) * KDIM + k0 + q * 8;
            const size_t offB = (size_t)(colBase + r) * KDIM + k0 + q * 8;
            cpa16(base + OFF_A + so, A + offA);
            cpa16(base + OFF_B + so, B + offB);
        }
        cpa_commit();
    };

    float acc[4][8][4];
    #pragma unroll
    for (int i = 0; i < 4; i++)
        #pragma unroll
        for (int j = 0; j < 8; j++)
            #pragma unroll
            for (int r = 0; r < 4; r++) acc[i][j][r] = 0.f;

    issue(0, 0);
    issue(1, 1);

    const int ja = lane >> 3;
    const int ra = lane & 7;
    const uint32_t aRowCol = (uint32_t)(((ja & 1) * 8 + ra) * ROWB + (ja >> 1) * 16);
    const uint32_t bRowCol = (uint32_t)((((lane >> 4) * 8) + ra) * ROWB + ((lane >> 3) & 1) * 16);

    for (int c = 0; c < NCH; c++) {
        if (c == NCH - 1)
            asm volatile("cp.async.wait_group 0;" ::: "memory");
        else
            asm volatile("cp.async.wait_group 1;" ::: "memory");
        __syncthreads();

        const int st = c & 1;
        const uint32_t base = sb + st * STAGEB;

        #pragma unroll
        for (int kb = 0; kb < 2; kb++) {
            uint32_t ah[4][4];
            #pragma unroll
            for (int mf = 0; mf < 4; mf++) {
                const uint32_t off = (uint32_t)((mBase + mf * 16) * ROWB + kb * 32) + aRowCol;
                ldsm_x4(ah[mf], base + OFF_A + off);
            }
            uint32_t bfr[8][2];
            #pragma unroll
            for (int nf2 = 0; nf2 < 4; nf2++) {
                const uint32_t off = (uint32_t)((nBase + nf2 * 16) * ROWB + kb * 32) + bRowCol;
                uint32_t t4[4];
                ldsm_x4(t4, base + OFF_B + off);
                bfr[nf2*2][0] = t4[0]; bfr[nf2*2][1] = t4[1];
                bfr[nf2*2+1][0] = t4[2]; bfr[nf2*2+1][1] = t4[3];
            }
            #pragma unroll
            for (int mf = 0; mf < 4; mf++)
                #pragma unroll
                for (int nf = 0; nf < 8; nf++)
                    mma_f16(acc[mf][nf], ah[mf], bfr[nf]);
        }
        __syncthreads();
        if (c + 2 < NCH) issue(c + 2, st);
    }

    #pragma unroll
    for (int mf = 0; mf < 4; mf++) {
        #pragma unroll
        for (int rp = 0; rp < 2; rp++) {
            const int m = rowBase + mBase + mf * 16 + (lane >> 2) + rp * 8;
            const int b = m >> 11;
            const int s_ = m & (SEQ - 1);
            #pragma unroll
            for (int nf = 0; nf < 8; nf++) {
                const int n0 = colBase + nBase + nf * 8 + (lane & 3) * 2;
                const float v0 = acc[mf][nf][rp * 2 + 0] + bias[n0];
                const float v1 = acc[mf][nf][rp * 2 + 1] + bias[n0 + 1];
                if (EPI == 0) {
                    const int h = n0 / 192;
                    const int rr = n0 - h * 192;
                    const size_t bhBase = (size_t)(b * HEADS + h) * SEQ + s_;
                    const uint32_t pk = pack_h2(__float2half(v0), __float2half(v1));
                    if (rr < 64) {
                        *(uint32_t*)&g_Qh[bhBase * DH + rr] = pk;
                    } else if (rr < 128) {
                        *(uint32_t*)&g_Kh[bhBase * DH + (rr - 64)] = pk;
                    } else {
                        *(uint32_t*)&g_Vh[bhBase * DH + (rr - 128)] = pk;
                    }
                } else {
                    *(float2*)&Cout[(size_t)m * DMODEL + n0] = make_float2(v0, v1);
                }
            }
        }
    }
}

// ---------------- pure fp16 flash attention, kv-tile 64, 3-stage KV pipeline ----------------
#define ROW2 144
#define FQ_BYTES (128*ROW2)            // 18432 (Q)
#define FK_BYTES (64*ROW2)             // 9216
#define FO_Q 0
#define FO_STAGE FQ_BYTES
#define FSTAGEB (2*FK_BYTES)           // 18432 (K | V)
#define NSTG 3
#define SMEM_FLASH (FO_STAGE + NSTG*FSTAGEB)   // 73728
#define NQT (SEQ/128)          // 16

__global__ __launch_bounds__(256, 2)
void flash_mma()
{
    extern __shared__ char smem[];
    const uint32_t sb = smem_u32(smem);
    const int tid = threadIdx.x;
    const int lane = tid & 31;
    const int w = tid >> 5;
    const int bx = blockIdx.x;       // 0..7
    const int bh = blockIdx.y;

    const int lr = lane >> 2;
    const int lc = (lane & 3) * 2;

    const __half* Qh = g_Qh + (size_t)bh * SEQ * DH;
    const __half* Kh = g_Kh + (size_t)bh * SEQ * DH;
    const __half* Vh = g_Vh + (size_t)bh * SEQ * DH;

    const int ja = lane >> 3;
    const int ra = lane & 7;
    const uint32_t aRowCol = (uint32_t)(((ja & 1) * 8 + ra) * ROW2 + (ja >> 1) * 16);
    const uint32_t bRowCol = (uint32_t)((((lane >> 4) * 8) + ra) * ROW2 + ((lane >> 3) & 1) * 16);
    const uint32_t qWarpOff = (uint32_t)(w * 16) * ROW2 + aRowCol;
    const uint32_t vTransOff = (uint32_t)((lane & 15) * ROW2 + (lane >> 4) * 16);

    auto issueKV = [&](int t, int st) {
        const int kv0 = t * 64;
        const uint32_t base = sb + FO_STAGE + st * FSTAGEB;
        #pragma unroll
        for (int j = 0; j < 2; j++) {
            const int u = tid + j * 256;
            const int r = u >> 3, c = u & 7;
            const uint32_t so = (uint32_t)(r * ROW2 + c * 16);
            const size_t off = (size_t)(kv0 + r) * DH + c * 8;
            cpa16(base + 0 * FK_BYTES + so, Kh + off);
            cpa16(base + 1 * FK_BYTES + so, Vh + off);
        }
        cpa_commit();
    };

    #pragma unroll 1
    for (int rep = 0; rep < 2; rep++) {
        const int qt = (rep == 0) ? bx : (NQT - 1 - bx);
        const int qb = qt * 128;
        const int nt = 2 * qt + 2;

        #pragma unroll
        for (int j = 0; j < 4; j++) {
            const int u = tid + j * 256;
            const int r = u >> 3, c = u & 7;
            const uint32_t so = (uint32_t)(r * ROW2 + c * 16);
            cpa16(sb + FO_Q + so, Qh + (size_t)(qb + r) * DH + c * 8);
        }
        issueKV(0, 0);
        issueKV(1, 1);

        float oacc[8][4];
        #pragma unroll
        for (int nf = 0; nf < 8; nf++)
            #pragma unroll
            for (int r = 0; r < 4; r++) oacc[nf][r] = 0.f;
        float m0 = -1e30f, m1 = -1e30f, l0 = 0.f, l1 = 0.f;

        const int qrow_last = qb + w * 16 + 15;

        for (int t = 0; t < nt; t++) {
            if (t == nt - 1)
                asm volatile("cp.async.wait_group 0;" ::: "memory");
            else
                asm volatile("cp.async.wait_group 1;" ::: "memory");
            __syncthreads();

            // 3-stage: issue tile t+2 into the buffer consumed at step t-1.
            // Every warp is past step t-1's reads (they reached this barrier),
            // so no trailing barrier is needed.
            if (t + 2 < nt) issueKV(t + 2, (t + 2) % NSTG);

            const int kv0 = t * 64;
            const uint32_t base = sb + FO_STAGE + (t % NSTG) * FSTAGEB;

            if (kv0 <= qrow_last) {
                float sacc[8][4];
                #pragma unroll
                for (int nf = 0; nf < 8; nf++)
                    #pragma unroll
                    for (int r = 0; r < 4; r++) sacc[nf][r] = 0.f;

                #pragma unroll
                for (int kf = 0; kf < 4; kf++) {
                    uint32_t qh4[4];
                    ldsm_x4(qh4, sb + FO_Q + qWarpOff + kf * 32);
                    uint32_t bb[8][2];
                    #pragma unroll
                    for (int nf2 = 0; nf2 < 4; nf2++) {
                        uint32_t t4[4];
                        ldsm_x4(t4, base + 0 * FK_BYTES +
                                (uint32_t)(nf2 * 16) * ROW2 + kf * 32 + bRowCol);
                        bb[nf2*2][0] = t4[0]; bb[nf2*2][1] = t4[1];
                        bb[nf2*2+1][0] = t4[2]; bb[nf2*2+1][1] = t4[3];
                    }
                    #pragma unroll
                    for (int nf = 0; nf < 8; nf++)
                        mma_f16(sacc[nf], qh4, bb[nf]);
                }

                const bool needMask = (kv0 + 63) > (qb + w * 16);
                const int row0 = qb + w * 16 + lr;
                const int row1 = row0 + 8;
                #pragma unroll
                for (int nf = 0; nf < 8; nf++) {
                    const int c0 = kv0 + nf * 8 + lc;
                    #pragma unroll
                    for (int r = 0; r < 4; r++) {
                        float v = sacc[nf][r] * 0.125f;
                        if (needMask) {
                            const int col = c0 + (r & 1);
                            const int row = (r < 2) ? row0 : row1;
                            if (col > row) v = -1e30f;
                        }
                        sacc[nf][r] = v;
                    }
                }

                float mx0 = -1e30f, mx1 = -1e30f;
                #pragma unroll
                for (int nf = 0; nf < 8; nf++) {
                    mx0 = fmaxf(mx0, fmaxf(sacc[nf][0], sacc[nf][1]));
                    mx1 = fmaxf(mx1, fmaxf(sacc[nf][2], sacc[nf][3]));
                }
                mx0 = fmaxf(mx0, __shfl_xor_sync(0xffffffffu, mx0, 1));
                mx0 = fmaxf(mx0, __shfl_xor_sync(0xffffffffu, mx0, 2));
                mx1 = fmaxf(mx1, __shfl_xor_sync(0xffffffffu, mx1, 1));
                mx1 = fmaxf(mx1, __shfl_xor_sync(0xffffffffu, mx1, 2));
                const float nm0 = fmaxf(m0, mx0);
                const float nm1 = fmaxf(m1, mx1);
                const float corr0 = __expf(m0 - nm0);
                const float corr1 = __expf(m1 - nm1);
                m0 = nm0; m1 = nm1;

                float rs0 = 0.f, rs1 = 0.f;
                #pragma unroll
                for (int nf = 0; nf < 8; nf++) {
                    float p0 = __expf(sacc[nf][0] - m0);
                    float p1 = __expf(sacc[nf][1] - m0);
                    float p2 = __expf(sacc[nf][2] - m1);
                    float p3 = __expf(sacc[nf][3] - m1);
                    sacc[nf][0] = p0; sacc[nf][1] = p1;
                    sacc[nf][2] = p2; sacc[nf][3] = p3;
                    rs0 += p0 + p1; rs1 += p2 + p3;
                }
                rs0 += __shfl_xor_sync(0xffffffffu, rs0, 1);
                rs0 += __shfl_xor_sync(0xffffffffu, rs0, 2);
                rs1 += __shfl_xor_sync(0xffffffffu, rs1, 1);
                rs1 += __shfl_xor_sync(0xffffffffu, rs1, 2);
                l0 = l0 * corr0 + rs0;
                l1 = l1 * corr1 + rs1;

                #pragma unroll
                for (int nf = 0; nf < 8; nf++) {
                    oacc[nf][0] *= corr0; oacc[nf][1] *= corr0;
                    oacc[nf][2] *= corr1; oacc[nf][3] *= corr1;
                }

                #pragma unroll
                for (int kf = 0; kf < 4; kf++) {
                    uint32_t ph[4];
                    ph[0] = pack_h2(__float2half(sacc[2*kf][0]),   __float2half(sacc[2*kf][1]));
                    ph[1] = pack_h2(__float2half(sacc[2*kf][2]),   __float2half(sacc[2*kf][3]));
                    ph[2] = pack_h2(__float2half(sacc[2*kf+1][0]), __float2half(sacc[2*kf+1][1]));
                    ph[3] = pack_h2(__float2half(sacc[2*kf+1][2]), __float2half(sacc[2*kf+1][3]));

                    uint32_t bv[8][2];
                    #pragma unroll
                    for (int nf2 = 0; nf2 < 4; nf2++) {
                        uint32_t t4[4];
                        ldsm_x4_t(t4, base + 1 * FK_BYTES +
                                  (uint32_t)(kf * 16) * ROW2 + nf2 * 32 + vTransOff);
                        bv[nf2*2][0] = t4[0]; bv[nf2*2][1] = t4[1];
                        bv[nf2*2+1][0] = t4[2]; bv[nf2*2+1][1] = t4[3];
                    }
                    #pragma unroll
                    for (int nf = 0; nf < 8; nf++)
                        mma_f16(oacc[nf], ph, bv[nf]);
                }
            }
        }
        __syncthreads();   // all reads of last tiles done before epilogue/rep-1 Q overwrite

        const float inv0 = 1.f / l0;
        const float inv1 = 1.f / l1;
        const int b = bh >> 4;
        const int h = bh & 15;
        const int row0 = qb + w * 16 + lr;
        const int row1 = row0 + 8;
        #pragma unroll
        for (int nf = 0; nf < 8; nf++) {
            const int col = h * 64 + nf * 8 + lc;
            const float v0 = oacc[nf][0] * inv0, v1 = oacc[nf][1] * inv0;
            const float v2 = oacc[nf][2] * inv1, v3 = oacc[nf][3] * inv1;
            const size_t i0 = ((size_t)(b * SEQ + row0)) * DMODEL + col;
            const size_t i1 = ((size_t)(b * SEQ + row1)) * DMODEL + col;
            *(uint32_t*)&g_attn_h[i0] = pack_h2(__float2half(v0), __float2half(v1));
            *(uint32_t*)&g_attn_h[i1] = pack_h2(__float2half(v2), __float2half(v3));
        }
        __syncthreads();
    }
}

// ---------------------------------------------------------------------------
extern "C" void kernel_launch(void* const* d_in, const int* in_sizes, int n_in,
                              void* d_out, int out_size)
{
    (void)in_sizes; (void)n_in; (void)out_size;
    const float* x    = (const float*)d_in[0];
    const float* Wqkv = (const float*)d_in[1];
    const float* bqkv = (const float*)d_in[2];
    const float* Wout = (const float*)d_in[3];
    const float* bout = (const float*)d_in[4];
    float* out = (float*)d_out;

    __half *xh, *wqh, *woh, *ah;
    cudaGetSymbolAddress((void**)&xh,  g_x_h);
    cudaGetSymbolAddress((void**)&wqh, g_wq_h);
    cudaGetSymbolAddress((void**)&woh, g_wo_h);
    cudaGetSymbolAddress((void**)&ah,  g_attn_h);

    cudaFuncSetAttribute(mma_gemm<0>, cudaFuncAttributeMaxDynamicSharedMemorySize, SMEM_GEMM);
    cudaFuncSetAttribute(mma_gemm<1>, cudaFuncAttributeMaxDynamicSharedMemorySize, SMEM_GEMM);
    cudaFuncSetAttribute(flash_mma, cudaFuncAttributeMaxDynamicSharedMemorySize, SMEM_FLASH);

    prep_kernel<<<8192, 256>>>(x, Wqkv, Wout, xh, wqh, woh);

    // QKV projection (pure fp16) -> Q/K/V fp16
    mma_gemm<0><<<dim3(NQKV / 128, MROWS / 128), 128, SMEM_GEMM>>>(
        xh, wqh, bqkv, nullptr);

    // pure fp16 causal flash attention, kv-tile 64, 3-stage pipeline
    flash_mma<<<dim3(NQT / 2, NBH), 256, SMEM_FLASH>>>();

    // output projection -> d_out
    mma_gemm<1><<<dim3(DMODEL / 128, MROWS / 128), 128, SMEM_GEMM>>>(
        ah, woh, bout, out);
}

// round 17
// speedup vs baseline: 1.1046x; 1.0529x over previous
#include <cuda_runtime.h>
#include <cuda_fp16.h>
#include <cstdint>

#define BATCH 2
#define SEQ 2048
#define HEADS 16
#define DH 64
#define DMODEL 1024
#define MROWS (BATCH*SEQ)   // 4096
#define KDIM 1024
#define NQKV 3072
#define NBH (BATCH*HEADS)   // 32

// ---------------- device scratch (allocation-free rule) ----------------
__device__ __half g_Qh[NBH*SEQ*DH];
__device__ __half g_Kh[NBH*SEQ*DH];
__device__ __half g_Vh[NBH*SEQ*DH];           // V fp16 [bh][s][d]
__device__ __half g_x_h [MROWS*KDIM];
__device__ __half g_wq_h[NQKV*KDIM];          // Wqkv^T [N,K] fp16
__device__ __half g_wo_h[DMODEL*KDIM];        // Wout^T [N,K] fp16
__device__ __half g_attn_h[MROWS*DMODEL];

// ---------------- helpers ----------------
__device__ __forceinline__ uint32_t smem_u32(const void* p) {
    uint32_t a;
    asm("{ .reg .u64 t; cvta.to.shared.u64 t, %1; cvt.u32.u64 %0, t; }" : "=r"(a) : "l"(p));
    return a;
}
__device__ __forceinline__ void cpa16(uint32_t dst, const void* src) {
    asm volatile("cp.async.cg.shared.global [%0], [%1], 16;" :: "r"(dst), "l"(src) : "memory");
}
__device__ __forceinline__ void cpa_commit() {
    asm volatile("cp.async.commit_group;" ::: "memory");
}
__device__ __forceinline__ void ldsm_x4(uint32_t* r, uint32_t addr) {
    asm volatile("ldmatrix.sync.aligned.m8n8.x4.shared.b16 {%0,%1,%2,%3}, [%4];"
        : "=r"(r[0]), "=r"(r[1]), "=r"(r[2]), "=r"(r[3]) : "r"(addr));
}
__device__ __forceinline__ void ldsm_x4_t(uint32_t* r, uint32_t addr) {
    asm volatile("ldmatrix.sync.aligned.m8n8.x4.trans.shared.b16 {%0,%1,%2,%3}, [%4];"
        : "=r"(r[0]), "=r"(r[1]), "=r"(r[2]), "=r"(r[3]) : "r"(addr));
}
__device__ __forceinline__ void mma_f16(float* c, const uint32_t* a, const uint32_t* b) {
    asm volatile(
        "mma.sync.aligned.m16n8k16.row.col.f32.f16.f16.f32 "
        "{%0,%1,%2,%3}, {%4,%5,%6,%7}, {%8,%9}, {%0,%1,%2,%3};"
        : "+f"(c[0]), "+f"(c[1]), "+f"(c[2]), "+f"(c[3])
        : "r"(a[0]), "r"(a[1]), "r"(a[2]), "r"(a[3]), "r"(b[0]), "r"(b[1]));
}
__device__ __forceinline__ uint32_t pack_h2(__half a, __half b) {
    return (uint32_t)__half_as_ushort(a) | ((uint32_t)__half_as_ushort(b) << 16);
}

// ---------------- fused preprocessing (round-14 proven) ----------------
__device__ __forceinline__ void do_transpose(const float* __restrict__ W,
                                             __half* __restrict__ th,
                                             int K, int N, int bx, int by, int tid) {
    __shared__ float t[32][33];
    const int tx = tid & 31, ty = tid >> 5;
    #pragma unroll
    for (int r = 0; r < 4; r++) {
        int k = by * 32 + ty + r * 8;
        int n = bx * 32 + tx;
        t[ty + r * 8][tx] = W[(size_t)k * N + n];
    }
    __syncthreads();
    #pragma unroll
    for (int r = 0; r < 4; r++) {
        int n = bx * 32 + ty + r * 8;
        int k = by * 32 + tx;
        th[(size_t)n * K + k] = __float2half(t[tx][ty + r * 8]);
    }
}

__global__ __launch_bounds__(256)
void prep_kernel(const float* __restrict__ x, const float* __restrict__ Wqkv,
                 const float* __restrict__ Wout,
                 __half* __restrict__ xh, __half* __restrict__ wqh,
                 __half* __restrict__ woh)
{
    const int blk = blockIdx.x;
    const int tid = threadIdx.x;
    if (blk < 4096) {
        const size_t i = (size_t)blk * 256 + tid;
        float4 v = ((const float4*)x)[i];
        ((uint2*)xh)[i] = make_uint2(pack_h2(__float2half(v.x), __float2half(v.y)),
                                     pack_h2(__float2half(v.z), __float2half(v.w)));
    } else if (blk < 7168) {
        const int b2 = blk - 4096;
        do_transpose(Wqkv, wqh, KDIM, NQKV, b2 % 96, b2 / 96, tid);
    } else {
        const int b2 = blk - 7168;
        do_transpose(Wout, woh, KDIM, DMODEL, b2 & 31, b2 >> 5, tid);
    }
}

// ---------------- pure fp16 GEMM: 4-stage pipeline, single barrier per chunk ----------------
#define BK 32
#define ROWB 80
#define MATB (128*ROWB)
#define OFF_A  0
#define OFF_B  MATB
#define STAGEB (2*MATB)          // 20480
#define GSTG 4
#define NCH (KDIM/BK)
#define SMEM_GEMM (GSTG*STAGEB)  // 81920

template<int EPI>
__global__ __launch_bounds__(128, 2)
void mma_gemm(const __half* __restrict__ A, const __half* __restrict__ B,
              const float* __restrict__ bias, float* __restrict__ Cout)
{
    extern __shared__ char smem[];
    const uint32_t sb = smem_u32(smem);
    const int tid = threadIdx.x;
    const int lane = tid & 31;
    const int wid = tid >> 5;
    const int rowBase = blockIdx.y * 128;
    const int colBase = blockIdx.x * 128;
    const int mBase = (wid & 1) * 64;
    const int nBase = (wid >> 1) * 64;

    auto issue = [&](int c) {
        const int k0 = c * BK;
        const uint32_t base = sb + (c & (GSTG - 1)) * STAGEB;
        #pragma unroll
        for (int j = 0; j < 4; j++) {
            const int u = tid + j * 128;
            const int r = u >> 2, q = u & 3;
            const uint32_t so = (uint32_t)(r * ROWB + q * 16);
            const size_t offA = (size_t)(rowBase + r) * KDIM + k0 + q * 8;
            const size_t offB = (size_t)(colBase + r) * KDIM + k0 + q * 8;
            cpa16(base + OFF_A + so, A + offA);
            cpa16(base + OFF_B + so, B + offB);
        }
        cpa_commit();
    };

    float acc[4][8][4];
    #pragma unroll
    for (int i = 0; i < 4; i++)
        #pragma unroll
        for (int j = 0; j < 8; j++)
            #pragma unroll
            for (int r = 0; r < 4; r++) acc[i][j][r] = 0.f;

    issue(0);
    issue(1);
    issue(2);

    const int ja = lane >> 3;
    const int ra = lane & 7;
    const uint32_t aRowCol = (uint32_t)(((ja & 1) * 8 + ra) * ROWB + (ja >> 1) * 16);
    const uint32_t bRowCol = (uint32_t)((((lane >> 4) * 8) + ra) * ROWB + ((lane >> 3) & 1) * 16);

    for (int c = 0; c < NCH; c++) {
        // group for chunk c must be complete; allow min(2, NCH-1-c) outstanding
        const int rem = NCH - 1 - c;
        if (rem >= 2)
            asm volatile("cp.async.wait_group 2;" ::: "memory");
        else if (rem == 1)
            asm volatile("cp.async.wait_group 1;" ::: "memory");
        else
            asm volatile("cp.async.wait_group 0;" ::: "memory");
        __syncthreads();

        // issue chunk c+3 into the buffer consumed at step c-1 (all warps past it)
        if (c + 3 < NCH) issue(c + 3);

        const uint32_t base = sb + (c & (GSTG - 1)) * STAGEB;

        #pragma unroll
        for (int kb = 0; kb < 2; kb++) {
            uint32_t ah[4][4];
            #pragma unroll
            for (int mf = 0; mf < 4; mf++) {
                const uint32_t off = (uint32_t)((mBase + mf * 16) * ROWB + kb * 32) + aRowCol;
                ldsm_x4(ah[mf], base + OFF_A + off);
            }
            uint32_t bfr[8][2];
            #pragma unroll
            for (int nf2 = 0; nf2 < 4; nf2++) {
                const uint32_t off = (uint32_t)((nBase + nf2 * 16) * ROWB + kb * 32) + bRowCol;
                uint32_t t4[4];
                ldsm_x4(t4, base + OFF_B + off);
                bfr[nf2*2][0] = t4[0]; bfr[nf2*2][1] = t4[1];
                bfr[nf2*2+1][0] = t4[2]; bfr[nf2*2+1][1] = t4[3];
            }
            #pragma unroll
            for (int mf = 0; mf < 4; mf++)
                #pragma unroll
                for (int nf = 0; nf < 8; nf++)
                    mma_f16(acc[mf][nf], ah[mf], bfr[nf]);
        }
    }

    #pragma unroll
    for (int mf = 0; mf < 4; mf++) {
        #pragma unroll
        for (int rp = 0; rp < 2; rp++) {
            const int m = rowBase + mBase + mf * 16 + (lane >> 2) + rp * 8;
            const int b = m >> 11;
            const int s_ = m & (SEQ - 1);
            #pragma unroll
            for (int nf = 0; nf < 8; nf++) {
                const int n0 = colBase + nBase + nf * 8 + (lane & 3) * 2;
                const float v0 = acc[mf][nf][rp * 2 + 0] + bias[n0];
                const float v1 = acc[mf][nf][rp * 2 + 1] + bias[n0 + 1];
                if (EPI == 0) {
                    const int h = n0 / 192;
                    const int rr = n0 - h * 192;
                    const size_t bhBase = (size_t)(b * HEADS + h) * SEQ + s_;
                    const uint32_t pk = pack_h2(__float2half(v0), __float2half(v1));
                    if (rr < 64) {
                        *(uint32_t*)&g_Qh[bhBase * DH + rr] = pk;
                    } else if (rr < 128) {
                        *(uint32_t*)&g_Kh[bhBase * DH + (rr - 64)] = pk;
                    } else {
                        *(uint32_t*)&g_Vh[bhBase * DH + (rr - 128)] = pk;
                    }
                } else {
                    *(float2*)&Cout[(size_t)m * DMODEL + n0] = make_float2(v0, v1);
                }
            }
        }
    }
}

// ---------------- pure fp16 flash attention, kv-tile 64, 3-stage KV pipeline (R16 proven) ----------------
#define ROW2 144
#define FQ_BYTES (128*ROW2)            // 18432 (Q)
#define FK_BYTES (64*ROW2)             // 9216
#define FO_Q 0
#define FO_STAGE FQ_BYTES
#define FSTAGEB (2*FK_BYTES)           // 18432 (K | V)
#define NSTG 3
#define SMEM_FLASH (FO_STAGE + NSTG*FSTAGEB)   // 73728
#define NQT (SEQ/128)          // 16

__global__ __launch_bounds__(256, 2)
void flash_mma()
{
    extern __shared__ char smem[];
    const uint32_t sb = smem_u32(smem);
    const int tid = threadIdx.x;
    const int lane = tid & 31;
    const int w = tid >> 5;
    const int bx = blockIdx.x;       // 0..7
    const int bh = blockIdx.y;

    const int lr = lane >> 2;
    const int lc = (lane & 3) * 2;

    const __half* Qh = g_Qh + (size_t)bh * SEQ * DH;
    const __half* Kh = g_Kh + (size_t)bh * SEQ * DH;
    const __half* Vh = g_Vh + (size_t)bh * SEQ * DH;

    const int ja = lane >> 3;
    const int ra = lane & 7;
    const uint32_t aRowCol = (uint32_t)(((ja & 1) * 8 + ra) * ROW2 + (ja >> 1) * 16);
    const uint32_t bRowCol = (uint32_t)((((lane >> 4) * 8) + ra) * ROW2 + ((lane >> 3) & 1) * 16);
    const uint32_t qWarpOff = (uint32_t)(w * 16) * ROW2 + aRowCol;
    const uint32_t vTransOff = (uint32_t)((lane & 15) * ROW2 + (lane >> 4) * 16);

    auto issueKV = [&](int t, int st) {
        const int kv0 = t * 64;
        const uint32_t base = sb + FO_STAGE + st * FSTAGEB;
        #pragma unroll
        for (int j = 0; j < 2; j++) {
            const int u = tid + j * 256;
            const int r = u >> 3, c = u & 7;
            const uint32_t so = (uint32_t)(r * ROW2 + c * 16);
            const size_t off = (size_t)(kv0 + r) * DH + c * 8;
            cpa16(base + 0 * FK_BYTES + so, Kh + off);
            cpa16(base + 1 * FK_BYTES + so, Vh + off);
        }
        cpa_commit();
    };

    #pragma unroll 1
    for (int rep = 0; rep < 2; rep++) {
        const int qt = (rep == 0) ? bx : (NQT - 1 - bx);
        const int qb = qt * 128;
        const int nt = 2 * qt + 2;

        #pragma unroll
        for (int j = 0; j < 4; j++) {
            const int u = tid + j * 256;
            const int r = u >> 3, c = u & 7;
            const uint32_t so = (uint32_t)(r * ROW2 + c * 16);
            cpa16(sb + FO_Q + so, Qh + (size_t)(qb + r) * DH + c * 8);
        }
        issueKV(0, 0);
        issueKV(1, 1);

        float oacc[8][4];
        #pragma unroll
        for (int nf = 0; nf < 8; nf++)
            #pragma unroll
            for (int r = 0; r < 4; r++) oacc[nf][r] = 0.f;
        float m0 = -1e30f, m1 = -1e30f, l0 = 0.f, l1 = 0.f;

        const int qrow_last = qb + w * 16 + 15;

        for (int t = 0; t < nt; t++) {
            if (t == nt - 1)
                asm volatile("cp.async.wait_group 0;" ::: "memory");
            else
                asm volatile("cp.async.wait_group 1;" ::: "memory");
            __syncthreads();

            if (t + 2 < nt) issueKV(t + 2, (t + 2) % NSTG);

            const int kv0 = t * 64;
            const uint32_t base = sb + FO_STAGE + (t % NSTG) * FSTAGEB;

            if (kv0 <= qrow_last) {
                float sacc[8][4];
                #pragma unroll
                for (int nf = 0; nf < 8; nf++)
                    #pragma unroll
                    for (int r = 0; r < 4; r++) sacc[nf][r] = 0.f;

                #pragma unroll
                for (int kf = 0; kf < 4; kf++) {
                    uint32_t qh4[4];
                    ldsm_x4(qh4, sb + FO_Q + qWarpOff + kf * 32);
                    uint32_t bb[8][2];
                    #pragma unroll
                    for (int nf2 = 0; nf2 < 4; nf2++) {
                        uint32_t t4[4];
                        ldsm_x4(t4, base + 0 * FK_BYTES +
                                (uint32_t)(nf2 * 16) * ROW2 + kf * 32 + bRowCol);
                        bb[nf2*2][0] = t4[0]; bb[nf2*2][1] = t4[1];
                        bb[nf2*2+1][0] = t4[2]; bb[nf2*2+1][1] = t4[3];
                    }
                    #pragma unroll
                    for (int nf = 0; nf < 8; nf++)
                        mma_f16(sacc[nf], qh4, bb[nf]);
                }

                const bool needMask = (kv0 + 63) > (qb + w * 16);
                const int row0 = qb + w * 16 + lr;
                const int row1 = row0 + 8;
                #pragma unroll
                for (int nf = 0; nf < 8; nf++) {
                    const int c0 = kv0 + nf * 8 + lc;
                    #pragma unroll
                    for (int r = 0; r < 4; r++) {
                        float v = sacc[nf][r] * 0.125f;
                        if (needMask) {
                            const int col = c0 + (r & 1);
                            const int row = (r < 2) ? row0 : row1;
                            if (col > row) v = -1e30f;
                        }
                        sacc[nf][r] = v;
                    }
                }

                float mx0 = -1e30f, mx1 = -1e30f;
                #pragma unroll
                for (int nf = 0; nf < 8; nf++) {
                    mx0 = fmaxf(mx0, fmaxf(sacc[nf][0], sacc[nf][1]));
                    mx1 = fmaxf(mx1, fmaxf(sacc[nf][2], sacc[nf][3]));
                }
                mx0 = fmaxf(mx0, __shfl_xor_sync(0xffffffffu, mx0, 1));
                mx0 = fmaxf(mx0, __shfl_xor_sync(0xffffffffu, mx0, 2));
                mx1 = fmaxf(mx1, __shfl_xor_sync(0xffffffffu, mx1, 1));
                mx1 = fmaxf(mx1, __shfl_xor_sync(0xffffffffu, mx1, 2));
                const float nm0 = fmaxf(m0, mx0);
                const float nm1 = fmaxf(m1, mx1);
                const float corr0 = __expf(m0 - nm0);
                const float corr1 = __expf(m1 - nm1);
                m0 = nm0; m1 = nm1;

                float rs0 = 0.f, rs1 = 0.f;
                #pragma unroll
                for (int nf = 0; nf < 8; nf++) {
                    float p0 = __expf(sacc[nf][0] - m0);
                    float p1 = __expf(sacc[nf][1] - m0);
                    float p2 = __expf(sacc[nf][2] - m1);
                    float p3 = __expf(sacc[nf][3] - m1);
                    sacc[nf][0] = p0; sacc[nf][1] = p1;
                    sacc[nf][2] = p2; sacc[nf][3] = p3;
                    rs0 += p0 + p1; rs1 += p2 + p3;
                }
                rs0 += __shfl_xor_sync(0xffffffffu, rs0, 1);
                rs0 += __shfl_xor_sync(0xffffffffu, rs0, 2);
                rs1 += __shfl_xor_sync(0xffffffffu, rs1, 1);
                rs1 += __shfl_xor_sync(0xffffffffu, rs1, 2);
                l0 = l0 * corr0 + rs0;
                l1 = l1 * corr1 + rs1;

                #pragma unroll
                for (int nf = 0; nf < 8; nf++) {
                    oacc[nf][0] *= corr0; oacc[nf][1] *= corr0;
                    oacc[nf][2] *= corr1; oacc[nf][3] *= corr1;
                }

                #pragma unroll
                for (int kf = 0; kf < 4; kf++) {
                    uint32_t ph[4];
                    ph[0] = pack_h2(__float2half(sacc[2*kf][0]),   __float2half(sacc[2*kf][1]));
                    ph[1] = pack_h2(__float2half(sacc[2*kf][2]),   __float2half(sacc[2*kf][3]));
                    ph[2] = pack_h2(__float2half(sacc[2*kf+1][0]), __float2half(sacc[2*kf+1][1]));
                    ph[3] = pack_h2(__float2half(sacc[2*kf+1][2]), __float2half(sacc[2*kf+1][3]));

                    uint32_t bv[8][2];
                    #pragma unroll
                    for (int nf2 = 0; nf2 < 4; nf2++) {
                        uint32_t t4[4];
                        ldsm_x4_t(t4, base + 1 * FK_BYTES +
                                  (uint32_t)(kf * 16) * ROW2 + nf2 * 32 + vTransOff);
                        bv[nf2*2][0] = t4[0]; bv[nf2*2][1] = t4[1];
                        bv[nf2*2+1][0] = t4[2]; bv[nf2*2+1][1] = t4[3];
                    }
                    #pragma unroll
                    for (int nf = 0; nf < 8; nf++)
                        mma_f16(oacc[nf], ph, bv[nf]);
                }
            }
        }
        __syncthreads();

        const float inv0 = 1.f / l0;
        const float inv1 = 1.f / l1;
        const int b = bh >> 4;
        const int h = bh & 15;
        const int row0 = qb + w * 16 + lr;
        const int row1 = row0 + 8;
        #pragma unroll
        for (int nf = 0; nf < 8; nf++) {
            const int col = h * 64 + nf * 8 + lc;
            const float v0 = oacc[nf][0] * inv0, v1 = oacc[nf][1] * inv0;
            const float v2 = oacc[nf][2] * inv1, v3 = oacc[nf][3] * inv1;
            const size_t i0 = ((size_t)(b * SEQ + row0)) * DMODEL + col;
            const size_t i1 = ((size_t)(b * SEQ + row1)) * DMODEL + col;
            *(uint32_t*)&g_attn_h[i0] = pack_h2(__float2half(v0), __float2half(v1));
            *(uint32_t*)&g_attn_h[i1] = pack_h2(__float2half(v2), __float2half(v3));
        }
        __syncthreads();
    }
}

// ---------------------------------------------------------------------------
extern "C" void kernel_launch(void* const* d_in, const int* in_sizes, int n_in,
                              void* d_out, int out_size)
{
    (void)in_sizes; (void)n_in; (void)out_size;
    const float* x    = (const float*)d_in[0];
    const float* Wqkv = (const float*)d_in[1];
    const float* bqkv = (const float*)d_in[2];
    const float* Wout = (const float*)d_in[3];
    const float* bout = (const float*)d_in[4];
    float* out = (float*)d_out;

    __half *xh, *wqh, *woh, *ah;
    cudaGetSymbolAddress((void**)&xh,  g_x_h);
    cudaGetSymbolAddress((void**)&wqh, g_wq_h);
    cudaGetSymbolAddress((void**)&woh, g_wo_h);
    cudaGetSymbolAddress((void**)&ah,  g_attn_h);

    cudaFuncSetAttribute(mma_gemm<0>, cudaFuncAttributeMaxDynamicSharedMemorySize, SMEM_GEMM);
    cudaFuncSetAttribute(mma_gemm<1>, cudaFuncAttributeMaxDynamicSharedMemorySize, SMEM_GEMM);
    cudaFuncSetAttribute(flash_mma, cudaFuncAttributeMaxDynamicSharedMemorySize, SMEM_FLASH);

    prep_kernel<<<8192, 256>>>(x, Wqkv, Wout, xh, wqh, woh);

    // QKV projection (pure fp16, 4-stage pipeline) -> Q/K/V fp16
    mma_gemm<0><<<dim3(NQKV / 128, MROWS / 128), 128, SMEM_GEMM>>>(
        xh, wqh, bqkv, nullptr);

    // pure fp16 causal flash attention, kv-tile 64, 3-stage pipeline
    flash_mma<<<dim3(NQT / 2, NBH), 256, SMEM_FLASH>>>();

    // output projection (4-stage pipeline) -> d_out
    mma_gemm<1><<<dim3(DMODEL / 128, MROWS / 128), 128, SMEM_GEMM>>>(
        ah, woh, bout, out);
}